// round 1
// baseline (speedup 1.0000x reference)
#include <cuda_runtime.h>

namespace {
constexpr int B_    = 2;
constexpr int SQ_   = 2048;
constexpr int SK_   = 2048;
constexpr int HQ_   = 32;
constexpr int HKV_  = 8;
constexpr int GQ_   = HQ_ / HKV_;   // 4
constexpr int D_    = 128;
constexpr int D4_   = D_ / 4;       // 32
constexpr int WIN_  = 512;
constexpr int QT_   = 32;           // q rows per block
constexpr int KT_   = 128;          // kv rows per tile
constexpr int NTMAX_ = 5;           // ceil((512+32)/128) = 5
constexpr int STRIPW_ = NTMAX_ * KT_;   // 640
constexpr float SCALE_ = 0.088388347648318447f;  // 1/sqrt(128)
constexpr float CAP_   = 30.0f;

// Shared memory layout. K/V tile buffer is shared (V pass reuses Ks).
// Rows padded to 33 float4 (132 floats): row stride 132 words ≡ 4 (mod 32)
// -> lane-strided row access in QK inner loop is bank-conflict-free.
struct Smem {
  float4 Qs[QT_][33];        // 16896 B
  float4 Ks[KT_][33];        // 67584 B (K tile, then reused as V tile)
  float  P[QT_][STRIPW_];    // 81920 B  exp-score strip, later clipped probs
};
// total = 166400 B < 227 KB
}  // namespace

__global__ __launch_bounds__(256, 1)
void attn_swa_kernel(const float* __restrict__ q, const float* __restrict__ k,
                     const float* __restrict__ v, float* __restrict__ out) {
  extern __shared__ char smem_raw[];
  Smem& sm = *reinterpret_cast<Smem*>(smem_raw);

  const int tid  = threadIdx.x;
  const int w    = tid >> 5;   // warp 0..7 -> q rows 4w..4w+3
  const int lane = tid & 31;
  const int qtile = blockIdx.x;
  const int h     = blockIdx.y;
  const int b     = blockIdx.z;
  const int qs   = qtile * QT_;
  const int kvh  = h / GQ_;

  const int lo   = (qs > WIN_) ? (qs - WIN_) : 0;   // first allowed kv
  const int kend = qs + QT_;                        // exclusive kv bound (<= SK)
  const int nt   = (kend - lo + KT_ - 1) / KT_;     // 1..5 tiles

  // ---- load Q tile (coalesced float4) ----
  const float4* qg = reinterpret_cast<const float4*>(q) +
                     (((size_t)b * SQ_ + qs) * HQ_ + h) * D4_;
  for (int m = tid; m < QT_ * D4_; m += 256) {
    int r = m >> 5, d4 = m & 31;
    sm.Qs[r][d4] = qg[(size_t)r * (HQ_ * D4_) + d4];
  }
  __syncthreads();

  const float4* kbase = reinterpret_cast<const float4*>(k) +
                        ((size_t)b * SK_ * HKV_ + kvh) * D4_;
  const float4* vbase = reinterpret_cast<const float4*>(v) +
                        ((size_t)b * SK_ * HKV_ + kvh) * D4_;

  // =======================  QK pass  =======================
  for (int t = 0; t < nt; ++t) {
    const int jbase = lo + t * KT_;
    // load K tile (guarded; OOB rows -> 0, their scores get masked anyway)
    for (int m = tid; m < KT_ * D4_; m += 256) {
      int r = m >> 5, d4 = m & 31;
      int j = jbase + r;
      float4 val = make_float4(0.f, 0.f, 0.f, 0.f);
      if (j < kend) val = kbase[(size_t)j * (HKV_ * D4_) + d4];
      sm.Ks[r][d4] = val;
    }
    __syncthreads();

    // 4x4 micro-tile: rows 4w+i, kv cols lane+32*jj
    float acc[4][4];
#pragma unroll
    for (int i = 0; i < 4; ++i)
#pragma unroll
      for (int jj = 0; jj < 4; ++jj) acc[i][jj] = 0.f;

#pragma unroll 4
    for (int d4 = 0; d4 < D4_; ++d4) {
      float4 qa[4], kc[4];
#pragma unroll
      for (int i = 0; i < 4; ++i) qa[i] = sm.Qs[4 * w + i][d4];      // broadcast
#pragma unroll
      for (int jj = 0; jj < 4; ++jj) kc[jj] = sm.Ks[lane + 32 * jj][d4];  // conflict-free
#pragma unroll
      for (int i = 0; i < 4; ++i)
#pragma unroll
        for (int jj = 0; jj < 4; ++jj) {
          acc[i][jj] += qa[i].x * kc[jj].x;
          acc[i][jj] += qa[i].y * kc[jj].y;
          acc[i][jj] += qa[i].z * kc[jj].z;
          acc[i][jj] += qa[i].w * kc[jj].w;
        }
    }

    // cap (30*tanh(s/30)), mask, exp -> strip.
    // tanh(y) = 1 - 2/(exp(2y)+1): no overflow, capped logits in (-30,30).
#pragma unroll
    for (int i = 0; i < 4; ++i) {
      const int ig = qs + 4 * w + i;
#pragma unroll
      for (int jj = 0; jj < 4; ++jj) {
        const int jg = jbase + lane + 32 * jj;
        const bool ok = (jg >= ig - WIN_) && (jg <= ig);
        float y2 = acc[i][jj] * (2.0f * SCALE_ / CAP_);
        float ez = __expf(y2);
        float th = 1.0f - __fdividef(2.0f, ez + 1.0f);
        float e  = ok ? __expf(CAP_ * th) : 0.0f;
        sm.P[4 * w + i][t * KT_ + lane + 32 * jj] = e;
      }
    }
    __syncthreads();
  }

  // =======  row sums + clip transform (in place, per-warp rows)  =======
  const int width = nt * KT_;
#pragma unroll
  for (int i = 0; i < 4; ++i) {
    const int r = 4 * w + i;
    float s = 0.f;
    for (int c = lane; c < width; c += 32) s += sm.P[r][c];
#pragma unroll
    for (int o = 16; o; o >>= 1) s += __shfl_xor_sync(0xffffffffu, s, o);
    const float c1 = 1.02f / s;   // s > 0 always (diagonal key always allowed)
    for (int c = lane; c < width; c += 32) {
      float p = sm.P[r][c] * c1 - 0.01f;        // masked: 0*c1-0.01 -> clamps to 0
      sm.P[r][c] = fminf(fmaxf(p, 0.0f), 1.0f);
    }
  }
  __syncthreads();

  // =======================  PV pass  =======================
  float4 oacc[4];
#pragma unroll
  for (int i = 0; i < 4; ++i) oacc[i] = make_float4(0.f, 0.f, 0.f, 0.f);

  for (int t = 0; t < nt; ++t) {
    const int jbase = lo + t * KT_;
    for (int m = tid; m < KT_ * D4_; m += 256) {
      int r = m >> 5, d4 = m & 31;
      int j = jbase + r;
      float4 val = make_float4(0.f, 0.f, 0.f, 0.f);
      if (j < kend) val = vbase[(size_t)j * (HKV_ * D4_) + d4];
      sm.Ks[r][d4] = val;   // reuse buffer as V tile
    }
    __syncthreads();

    const int jmax = min(KT_, kend - jbase);
#pragma unroll 2
    for (int jj = 0; jj < jmax; ++jj) {
      float4 vv = sm.Ks[jj][lane];              // conflict-free (consecutive f4)
#pragma unroll
      for (int i = 0; i < 4; ++i) {
        float p = sm.P[4 * w + i][t * KT_ + jj];  // broadcast
        oacc[i].x += p * vv.x;
        oacc[i].y += p * vv.y;
        oacc[i].z += p * vv.z;
        oacc[i].w += p * vv.w;
      }
    }
    __syncthreads();
  }

  // ---- write output (coalesced float4) ----
  float4* og = reinterpret_cast<float4*>(out);
#pragma unroll
  for (int i = 0; i < 4; ++i) {
    size_t idx = (((size_t)b * SQ_ + qs + 4 * w + i) * HQ_ + h) * D4_ + lane;
    og[idx] = oacc[i];
  }
}

extern "C" void kernel_launch(void* const* d_in, const int* in_sizes, int n_in,
                              void* d_out, int out_size) {
  (void)in_sizes; (void)n_in; (void)out_size;
  const float* q = (const float*)d_in[0];
  const float* k = (const float*)d_in[1];
  const float* v = (const float*)d_in[2];
  float* out = (float*)d_out;

  static_assert(sizeof(Smem) <= 227 * 1024, "smem over budget");
  cudaFuncSetAttribute(attn_swa_kernel,
                       cudaFuncAttributeMaxDynamicSharedMemorySize,
                       (int)sizeof(Smem));
  dim3 grid(SQ_ / QT_, HQ_, B_);
  attn_swa_kernel<<<grid, 256, sizeof(Smem)>>>(q, k, v, out);
}

// round 2
// speedup vs baseline: 1.0011x; 1.0011x over previous
#include <cuda_runtime.h>

namespace {
constexpr int B_    = 2;
constexpr int SQ_   = 2048;
constexpr int SK_   = 2048;
constexpr int HQ_   = 32;
constexpr int HKV_  = 8;
constexpr int GQ_   = HQ_ / HKV_;   // 4
constexpr int D_    = 128;
constexpr int D4_   = D_ / 4;       // 32
constexpr int WIN_  = 512;
constexpr int QT_   = 32;           // q rows per block
constexpr int KT_   = 128;          // kv rows per tile
constexpr int NTMAX_ = 5;           // ceil((512+32)/128) = 5
constexpr int STRIPW_ = NTMAX_ * KT_;   // 640
constexpr float SCALE_ = 0.088388347648318447f;  // 1/sqrt(128)
constexpr float CAP_   = 30.0f;

// Shared memory layout. K/V tile buffer is shared (V pass reuses Ks).
// Rows padded to 33 float4 (132 floats): row stride 132 words ≡ 4 (mod 32)
// -> lane-strided row access in QK inner loop is bank-conflict-free.
struct Smem {
  float4 Qs[QT_][33];        // 16896 B
  float4 Ks[KT_][33];        // 67584 B (K tile, then reused as V tile)
  float  P[QT_][STRIPW_];    // 81920 B  exp-score strip, later clipped probs
};
// total = 166400 B < 227 KB
}  // namespace

__global__ __launch_bounds__(256, 1)
void attn_swa_kernel(const float* __restrict__ q, const float* __restrict__ k,
                     const float* __restrict__ v, float* __restrict__ out) {
  extern __shared__ char smem_raw[];
  Smem& sm = *reinterpret_cast<Smem*>(smem_raw);

  const int tid  = threadIdx.x;
  const int w    = tid >> 5;   // warp 0..7 -> q rows 4w..4w+3
  const int lane = tid & 31;
  const int qtile = blockIdx.x;
  const int h     = blockIdx.y;
  const int b     = blockIdx.z;
  const int qs   = qtile * QT_;
  const int kvh  = h / GQ_;

  const int lo   = (qs > WIN_) ? (qs - WIN_) : 0;   // first allowed kv
  const int kend = qs + QT_;                        // exclusive kv bound (<= SK)
  const int nt   = (kend - lo + KT_ - 1) / KT_;     // 1..5 tiles

  // ---- load Q tile (coalesced float4) ----
  const float4* qg = reinterpret_cast<const float4*>(q) +
                     (((size_t)b * SQ_ + qs) * HQ_ + h) * D4_;
  for (int m = tid; m < QT_ * D4_; m += 256) {
    int r = m >> 5, d4 = m & 31;
    sm.Qs[r][d4] = qg[(size_t)r * (HQ_ * D4_) + d4];
  }
  __syncthreads();

  const float4* kbase = reinterpret_cast<const float4*>(k) +
                        ((size_t)b * SK_ * HKV_ + kvh) * D4_;
  const float4* vbase = reinterpret_cast<const float4*>(v) +
                        ((size_t)b * SK_ * HKV_ + kvh) * D4_;

  // =======================  QK pass  =======================
  for (int t = 0; t < nt; ++t) {
    const int jbase = lo + t * KT_;
    // load K tile (guarded; OOB rows -> 0, their scores get masked anyway)
    for (int m = tid; m < KT_ * D4_; m += 256) {
      int r = m >> 5, d4 = m & 31;
      int j = jbase + r;
      float4 val = make_float4(0.f, 0.f, 0.f, 0.f);
      if (j < kend) val = kbase[(size_t)j * (HKV_ * D4_) + d4];
      sm.Ks[r][d4] = val;
    }
    __syncthreads();

    // 4x4 micro-tile: rows 4w+i, kv cols lane+32*jj
    float acc[4][4];
#pragma unroll
    for (int i = 0; i < 4; ++i)
#pragma unroll
      for (int jj = 0; jj < 4; ++jj) acc[i][jj] = 0.f;

#pragma unroll 4
    for (int d4 = 0; d4 < D4_; ++d4) {
      float4 qa[4], kc[4];
#pragma unroll
      for (int i = 0; i < 4; ++i) qa[i] = sm.Qs[4 * w + i][d4];      // broadcast
#pragma unroll
      for (int jj = 0; jj < 4; ++jj) kc[jj] = sm.Ks[lane + 32 * jj][d4];  // conflict-free
#pragma unroll
      for (int i = 0; i < 4; ++i)
#pragma unroll
        for (int jj = 0; jj < 4; ++jj) {
          acc[i][jj] += qa[i].x * kc[jj].x;
          acc[i][jj] += qa[i].y * kc[jj].y;
          acc[i][jj] += qa[i].z * kc[jj].z;
          acc[i][jj] += qa[i].w * kc[jj].w;
        }
    }

    // cap (30*tanh(s/30)), mask, exp -> strip.
    // tanh(y) = 1 - 2/(exp(2y)+1): no overflow, capped logits in (-30,30).
#pragma unroll
    for (int i = 0; i < 4; ++i) {
      const int ig = qs + 4 * w + i;
#pragma unroll
      for (int jj = 0; jj < 4; ++jj) {
        const int jg = jbase + lane + 32 * jj;
        const bool ok = (jg >= ig - WIN_) && (jg <= ig);
        float y2 = acc[i][jj] * (2.0f * SCALE_ / CAP_);
        float ez = __expf(y2);
        float th = 1.0f - __fdividef(2.0f, ez + 1.0f);
        float e  = ok ? __expf(CAP_ * th) : 0.0f;
        sm.P[4 * w + i][t * KT_ + lane + 32 * jj] = e;
      }
    }
    __syncthreads();
  }

  // =======  row sums + clip transform (in place, per-warp rows)  =======
  const int width = nt * KT_;
#pragma unroll
  for (int i = 0; i < 4; ++i) {
    const int r = 4 * w + i;
    float s = 0.f;
    for (int c = lane; c < width; c += 32) s += sm.P[r][c];
#pragma unroll
    for (int o = 16; o; o >>= 1) s += __shfl_xor_sync(0xffffffffu, s, o);
    const float c1 = 1.02f / s;   // s > 0 always (diagonal key always allowed)
    for (int c = lane; c < width; c += 32) {
      float p = sm.P[r][c] * c1 - 0.01f;        // masked: 0*c1-0.01 -> clamps to 0
      sm.P[r][c] = fminf(fmaxf(p, 0.0f), 1.0f);
    }
  }
  __syncthreads();

  // =======================  PV pass  =======================
  float4 oacc[4];
#pragma unroll
  for (int i = 0; i < 4; ++i) oacc[i] = make_float4(0.f, 0.f, 0.f, 0.f);

  for (int t = 0; t < nt; ++t) {
    const int jbase = lo + t * KT_;
    for (int m = tid; m < KT_ * D4_; m += 256) {
      int r = m >> 5, d4 = m & 31;
      int j = jbase + r;
      float4 val = make_float4(0.f, 0.f, 0.f, 0.f);
      if (j < kend) val = vbase[(size_t)j * (HKV_ * D4_) + d4];
      sm.Ks[r][d4] = val;   // reuse buffer as V tile
    }
    __syncthreads();

    const int jmax = min(KT_, kend - jbase);
#pragma unroll 2
    for (int jj = 0; jj < jmax; ++jj) {
      float4 vv = sm.Ks[jj][lane];              // conflict-free (consecutive f4)
#pragma unroll
      for (int i = 0; i < 4; ++i) {
        float p = sm.P[4 * w + i][t * KT_ + jj];  // broadcast
        oacc[i].x += p * vv.x;
        oacc[i].y += p * vv.y;
        oacc[i].z += p * vv.z;
        oacc[i].w += p * vv.w;
      }
    }
    __syncthreads();
  }

  // ---- write output (coalesced float4) ----
  float4* og = reinterpret_cast<float4*>(out);
#pragma unroll
  for (int i = 0; i < 4; ++i) {
    size_t idx = (((size_t)b * SQ_ + qs + 4 * w + i) * HQ_ + h) * D4_ + lane;
    og[idx] = oacc[i];
  }
}

extern "C" void kernel_launch(void* const* d_in, const int* in_sizes, int n_in,
                              void* d_out, int out_size) {
  (void)in_sizes; (void)n_in; (void)out_size;
  const float* q = (const float*)d_in[0];
  const float* k = (const float*)d_in[1];
  const float* v = (const float*)d_in[2];
  float* out = (float*)d_out;

  static_assert(sizeof(Smem) <= 227 * 1024, "smem over budget");
  cudaFuncSetAttribute(attn_swa_kernel,
                       cudaFuncAttributeMaxDynamicSharedMemorySize,
                       (int)sizeof(Smem));
  dim3 grid(SQ_ / QT_, HQ_, B_);
  attn_swa_kernel<<<grid, 256, sizeof(Smem)>>>(q, k, v, out);
}